// round 5
// baseline (speedup 1.0000x reference)
#include <cuda_runtime.h>
#include <cstdint>

#define Bdim 4
#define Hdim 512
#define Wdim 512
#define C_TOTAL 25
#define CS (Hdim * Wdim)

typedef unsigned long long u64;

__device__ __forceinline__ void fma2(u64& d, u64 a, u64 b) {
    asm("fma.rn.f32x2 %0, %1, %2, %0;" : "+l"(d) : "l"(a), "l"(b));
}
__device__ __forceinline__ u64 dup2(float v) {
    u64 r; asm("mov.b64 %0, {%1, %1};" : "=l"(r) : "f"(v)); return r;
}
__device__ __forceinline__ u64 pack2(float lo, float hi) {
    u64 r; asm("mov.b64 %0, {%1, %2};" : "=l"(r) : "f"(lo), "f"(hi)); return r;
}
__device__ __forceinline__ void unpack2(u64 v, float& lo, float& hi) {
    asm("mov.b64 {%0, %1}, %2;" : "=f"(lo), "=f"(hi) : "l"(v));
}
__device__ __forceinline__ uint32_t smaddr(const void* p) {
    return (uint32_t)__cvta_generic_to_shared(p);
}
__device__ __forceinline__ void cp16(uint32_t dst, const float* src) {
    asm volatile("cp.async.ca.shared.global [%0], [%1], 16;" :: "r"(dst), "l"(src));
}
__device__ __forceinline__ void cp4(uint32_t dst, const float* src) {
    asm volatile("cp.async.ca.shared.global [%0], [%1], 4;" :: "r"(dst), "l"(src));
}
__device__ __forceinline__ void cpcommit() { asm volatile("cp.async.commit_group;"); }
template<int N> __device__ __forceinline__ void cpwait() {
    asm volatile("cp.async.wait_group %0;" :: "n"(N));
}

// ---------------------------------------------------------------------------
// Tiled dilated 3x3 conv layer, spatial-f32x2 packed.
// Block: 128 threads = 4 warps; warp w = row-group w (R=16 rows), lanes = 32
// column-pairs covering TW=64 output columns. Tile: 64x64 outputs.
// Per input channel: cp.async-fill the (64+2D)x(64+2PAD) patch (reflect applied
// at fill) into one of 3 rotating smem buffers; compute reads f32x2 taps.
// One __syncthreads per channel (3-buffer rotation makes WAR distance 2 mod 3).
// ---------------------------------------------------------------------------
template<int N_IN, int D>
__global__ __launch_bounds__(128)
void conv_layer(const float* __restrict__ g, float* __restrict__ outg,
                const float* __restrict__ wgt, const float* __restrict__ bias2p)
{
    constexpr int R = 16;
    constexpr int TW = 64;
    constexpr int TH = 64;
    constexpr int NT = 128;
    constexpr int PAD = (D + 3) & ~3;           // even, 16B-aligned col halo
    constexpr int TCW = TW + 2 * PAD;           // even
    constexpr int TROWS = TH + 2 * D;
    constexpr int TS = TROWS * TCW;             // even
    constexpr int WS = (18 * N_IN + 3) & ~3;    // weight floats, padded

    extern __shared__ float sm[];
    float* ws = sm;                  // [ic][k=0..8][oc] interleaved
    float* tiles = sm + WS;          // 3 buffers of TS floats

    const int tid = threadIdx.x;
    const int tc  = tid & 31;        // column-pair within warp
    const int rg  = tid >> 5;        // row group (warp)
    const int c0 = blockIdx.x * TW, r0 = blockIdx.y * TH, b = blockIdx.z;
    const int gr0 = r0 - D, gc0 = c0 - PAD;

    for (int i = tid; i < 9 * N_IN; i += NT) {
        ws[2 * i]     = wgt[i];               // oc0 weight k=i
        ws[2 * i + 1] = wgt[9 * N_IN + i];    // oc1 weight k=i
    }

    const float* plane0 = g + (size_t)(b * C_TOTAL) * CS;

    auto fill = [&](int ic, float* dstbuf) {
        const float* plane = plane0 + (size_t)ic * CS;
        uint32_t dbase = smaddr(dstbuf);
        #pragma unroll 1
        for (int idx = tid; idx < TROWS * (TCW / 4); idx += NT) {
            int tr = idx / (TCW / 4);
            int cc = idx - tr * (TCW / 4);
            int gr = gr0 + tr;
            if (gr < 0) gr = -gr; else if (gr >= Hdim) gr = 2 * Hdim - 2 - gr;
            int gc = gc0 + cc * 4;
            uint32_t dst = dbase + (uint32_t)(tr * TCW + cc * 4) * 4u;
            const float* srow = plane + (size_t)gr * Wdim;
            if (gc >= 0 && gc + 4 <= Wdim) {
                cp16(dst, srow + gc);
            } else {
                #pragma unroll
                for (int k = 0; k < 4; ++k) {
                    int c = gc + k;
                    if (c < 0) c = -c; else if (c >= Wdim) c = 2 * Wdim - 2 - c;
                    cp4(dst + 4u * k, srow + c);
                }
            }
        }
    };

    u64 accA[R], accB[R];
    {
        u64 bA = dup2(bias2p[0]), bB = dup2(bias2p[1]);
        #pragma unroll
        for (int m = 0; m < R; ++m) { accA[m] = bA; accB[m] = bB; }
    }

    fill(0, tiles); cpcommit();

    #pragma unroll 1
    for (int ic = 0; ic < N_IN; ++ic) {
        if (ic + 1 < N_IN) {
            fill(ic + 1, tiles + ((ic + 1) % 3) * TS);
            cpcommit();
            cpwait<1>();            // this thread's fill(ic) parts drained
        } else {
            cpwait<0>();
        }
        __syncthreads();            // fill(ic) visible block-wide (covers ws on ic=0)

        u64 wA[9], wB[9];
        #pragma unroll
        for (int k = 0; k < 9; ++k) {
            wA[k] = dup2(ws[ic * 18 + 2 * k]);
            wB[k] = dup2(ws[ic * 18 + 2 * k + 1]);
        }

        const float* base = tiles + (ic % 3) * TS + (size_t)(rg * R) * TCW + (PAD + 2 * tc);
        #pragma unroll
        for (int j = 0; j < R + 2 * D; ++j) {
            const float* rp = base + j * TCW;
            u64 vc = *(const u64*)rp;                 // aligned (PAD even, TCW even)
            u64 vl, vr;
            if (D % 2 == 0) {
                vl = *(const u64*)(rp - D);
                vr = *(const u64*)(rp + D);
            } else {
                vl = pack2(rp[-D], rp[-D + 1]);
                vr = pack2(rp[ D], rp[ D + 1]);
            }
            if (j < R) {
                fma2(accA[j], wA[0], vl); fma2(accA[j], wA[1], vc); fma2(accA[j], wA[2], vr);
                fma2(accB[j], wB[0], vl); fma2(accB[j], wB[1], vc); fma2(accB[j], wB[2], vr);
            }
            if (j >= D && j < R + D) {
                fma2(accA[j - D], wA[3], vl); fma2(accA[j - D], wA[4], vc); fma2(accA[j - D], wA[5], vr);
                fma2(accB[j - D], wB[3], vl); fma2(accB[j - D], wB[4], vc); fma2(accB[j - D], wB[5], vr);
            }
            if (j >= 2 * D) {
                fma2(accA[j - 2 * D], wA[6], vl); fma2(accA[j - 2 * D], wA[7], vc); fma2(accA[j - 2 * D], wA[8], vr);
                fma2(accB[j - 2 * D], wB[6], vl); fma2(accB[j - 2 * D], wB[7], vc); fma2(accB[j - 2 * D], wB[8], vr);
            }
        }
        // no trailing sync needed: next fill targets buffer (ic+2)%3, and the
        // per-iteration barrier bounds stragglers to compute(ic-1) on (ic-1)%3.
    }

    float* oA = outg + ((size_t)(b * C_TOTAL + N_IN)) * CS
                     + (size_t)(r0 + rg * R) * Wdim + (c0 + 2 * tc);
    #pragma unroll
    for (int m = 0; m < R; ++m) {
        float lo, hi;
        unpack2(accA[m], lo, hi);
        *(float2*)(oA + (size_t)m * Wdim) = make_float2(fmaxf(lo, 0.f), fmaxf(hi, 0.f));
        unpack2(accB[m], lo, hi);
        *(float2*)(oA + CS + (size_t)m * Wdim) = make_float2(fmaxf(lo, 0.f), fmaxf(hi, 0.f));
    }
}

__global__ void copy_in_kernel(const float4* __restrict__ x, float4* __restrict__ out) {
    int idx = blockIdx.x * blockDim.x + threadIdx.x;
    const int P4 = CS / 4;
    if (idx >= Bdim * P4) return;
    int b = idx / P4;
    int p = idx - b * P4;
    out[(size_t)b * (C_TOTAL * P4) + p] = x[idx];
}

template<int N_IN, int D>
static void launch_layer(float* out, const float* w, const float* bias, int layer) {
    constexpr int PAD = (D + 3) & ~3;
    constexpr int TCW = 64 + 2 * PAD;
    constexpr int TROWS = 64 + 2 * D;
    constexpr int WS = (18 * N_IN + 3) & ~3;
    constexpr int SMEM = (WS + 3 * TROWS * TCW) * 4;
    cudaFuncSetAttribute(conv_layer<N_IN, D>,
                         cudaFuncAttributeMaxDynamicSharedMemorySize, SMEM);
    conv_layer<N_IN, D><<<dim3(Wdim / 64, Hdim / 64, Bdim), 128, SMEM>>>(
        out, out, w, bias + 2 * layer);
}

extern "C" void kernel_launch(void* const* d_in, const int* in_sizes, int n_in,
                              void* d_out, int out_size) {
    const float* x    = (const float*)d_in[0];
    const float* bias = (const float*)d_in[1];
    float* out = (float*)d_out;

    {
        int total4 = Bdim * CS / 4;
        copy_in_kernel<<<(total4 + 255) / 256, 256>>>((const float4*)x, (float4*)out);
    }

    launch_layer< 1,  1>(out, (const float*)d_in[2],  bias, 0);
    launch_layer< 3,  2>(out, (const float*)d_in[3],  bias, 1);
    launch_layer< 5,  3>(out, (const float*)d_in[4],  bias, 2);
    launch_layer< 7,  4>(out, (const float*)d_in[5],  bias, 3);
    launch_layer< 9,  5>(out, (const float*)d_in[6],  bias, 4);
    launch_layer<11,  6>(out, (const float*)d_in[7],  bias, 5);
    launch_layer<13,  7>(out, (const float*)d_in[8],  bias, 6);
    launch_layer<15,  8>(out, (const float*)d_in[9],  bias, 7);
    launch_layer<17,  9>(out, (const float*)d_in[10], bias, 8);
    launch_layer<19, 10>(out, (const float*)d_in[11], bias, 9);
    launch_layer<21, 11>(out, (const float*)d_in[12], bias, 10);
    launch_layer<23, 12>(out, (const float*)d_in[13], bias, 11);
}

// round 6
// speedup vs baseline: 1.0010x; 1.0010x over previous
#include <cuda_runtime.h>
#include <cstdint>

#define Bdim 4
#define Hdim 512
#define Wdim 512
#define C_TOTAL 25
#define CS (Hdim * Wdim)

typedef unsigned long long u64;

__device__ __forceinline__ void fma2(u64& d, u64 a, u64 b) {
    asm("fma.rn.f32x2 %0, %1, %2, %0;" : "+l"(d) : "l"(a), "l"(b));
}
__device__ __forceinline__ u64 dup2(float v) {
    u64 r; asm("mov.b64 %0, {%1, %1};" : "=l"(r) : "f"(v)); return r;
}
__device__ __forceinline__ u64 pack2(float lo, float hi) {
    u64 r; asm("mov.b64 %0, {%1, %2};" : "=l"(r) : "f"(lo), "f"(hi)); return r;
}
__device__ __forceinline__ void unpack2(u64 v, float& lo, float& hi) {
    asm("mov.b64 {%0, %1}, %2;" : "=f"(lo), "=f"(hi) : "l"(v));
}
__device__ __forceinline__ uint32_t smaddr(const void* p) {
    return (uint32_t)__cvta_generic_to_shared(p);
}
__device__ __forceinline__ void cp16(uint32_t dst, const float* src) {
    asm volatile("cp.async.ca.shared.global [%0], [%1], 16;" :: "r"(dst), "l"(src));
}
__device__ __forceinline__ void cp4(uint32_t dst, const float* src) {
    asm volatile("cp.async.ca.shared.global [%0], [%1], 4;" :: "r"(dst), "l"(src));
}
__device__ __forceinline__ void cpcommit() { asm volatile("cp.async.commit_group;"); }
template<int N> __device__ __forceinline__ void cpwait() {
    asm volatile("cp.async.wait_group %0;" :: "n"(N));
}

// ---------------------------------------------------------------------------
// Tiled dilated 3x3 conv layer, spatial-f32x2 packed.
// Block: 128 threads = 4 warps; warp w = row-group w (R=16 rows), lanes = 32
// column-pairs covering TW=64 output columns. Tile: 64x64 outputs.
// Per input channel: cp.async-fill the (64+2D)x(64+2PAD) patch (reflect applied
// at fill) into one of 3 rotating smem buffers; compute reads f32x2 taps.
// One __syncthreads per channel (3-buffer rotation makes WAR distance 2 mod 3).
// ---------------------------------------------------------------------------
template<int N_IN, int D>
__global__ __launch_bounds__(128)
void conv_layer(const float* __restrict__ g, float* __restrict__ outg,
                const float* __restrict__ wgt, const float* __restrict__ bias2p)
{
    constexpr int R = 16;
    constexpr int TW = 64;
    constexpr int TH = 64;
    constexpr int NT = 128;
    constexpr int PAD = (D + 3) & ~3;           // even, 16B-aligned col halo
    constexpr int TCW = TW + 2 * PAD;           // even
    constexpr int TROWS = TH + 2 * D;
    constexpr int TS = TROWS * TCW;             // even
    constexpr int WS = (18 * N_IN + 3) & ~3;    // weight floats, padded

    extern __shared__ float sm[];
    float* ws = sm;                  // [ic][k=0..8][oc] interleaved
    float* tiles = sm + WS;          // 3 buffers of TS floats

    const int tid = threadIdx.x;
    const int tc  = tid & 31;        // column-pair within warp
    const int rg  = tid >> 5;        // row group (warp)
    const int c0 = blockIdx.x * TW, r0 = blockIdx.y * TH, b = blockIdx.z;
    const int gr0 = r0 - D, gc0 = c0 - PAD;

    for (int i = tid; i < 9 * N_IN; i += NT) {
        ws[2 * i]     = wgt[i];               // oc0 weight k=i
        ws[2 * i + 1] = wgt[9 * N_IN + i];    // oc1 weight k=i
    }

    const float* plane0 = g + (size_t)(b * C_TOTAL) * CS;

    auto fill = [&](int ic, float* dstbuf) {
        const float* plane = plane0 + (size_t)ic * CS;
        uint32_t dbase = smaddr(dstbuf);
        #pragma unroll 1
        for (int idx = tid; idx < TROWS * (TCW / 4); idx += NT) {
            int tr = idx / (TCW / 4);
            int cc = idx - tr * (TCW / 4);
            int gr = gr0 + tr;
            if (gr < 0) gr = -gr; else if (gr >= Hdim) gr = 2 * Hdim - 2 - gr;
            int gc = gc0 + cc * 4;
            uint32_t dst = dbase + (uint32_t)(tr * TCW + cc * 4) * 4u;
            const float* srow = plane + (size_t)gr * Wdim;
            if (gc >= 0 && gc + 4 <= Wdim) {
                cp16(dst, srow + gc);
            } else {
                #pragma unroll
                for (int k = 0; k < 4; ++k) {
                    int c = gc + k;
                    if (c < 0) c = -c; else if (c >= Wdim) c = 2 * Wdim - 2 - c;
                    cp4(dst + 4u * k, srow + c);
                }
            }
        }
    };

    u64 accA[R], accB[R];
    {
        u64 bA = dup2(bias2p[0]), bB = dup2(bias2p[1]);
        #pragma unroll
        for (int m = 0; m < R; ++m) { accA[m] = bA; accB[m] = bB; }
    }

    fill(0, tiles); cpcommit();

    #pragma unroll 1
    for (int ic = 0; ic < N_IN; ++ic) {
        if (ic + 1 < N_IN) {
            fill(ic + 1, tiles + ((ic + 1) % 3) * TS);
            cpcommit();
            cpwait<1>();            // this thread's fill(ic) parts drained
        } else {
            cpwait<0>();
        }
        __syncthreads();            // fill(ic) visible block-wide (covers ws on ic=0)

        u64 wA[9], wB[9];
        #pragma unroll
        for (int k = 0; k < 9; ++k) {
            wA[k] = dup2(ws[ic * 18 + 2 * k]);
            wB[k] = dup2(ws[ic * 18 + 2 * k + 1]);
        }

        const float* base = tiles + (ic % 3) * TS + (size_t)(rg * R) * TCW + (PAD + 2 * tc);
        #pragma unroll
        for (int j = 0; j < R + 2 * D; ++j) {
            const float* rp = base + j * TCW;
            u64 vc = *(const u64*)rp;                 // aligned (PAD even, TCW even)
            u64 vl, vr;
            if (D % 2 == 0) {
                vl = *(const u64*)(rp - D);
                vr = *(const u64*)(rp + D);
            } else {
                vl = pack2(rp[-D], rp[-D + 1]);
                vr = pack2(rp[ D], rp[ D + 1]);
            }
            if (j < R) {
                fma2(accA[j], wA[0], vl); fma2(accA[j], wA[1], vc); fma2(accA[j], wA[2], vr);
                fma2(accB[j], wB[0], vl); fma2(accB[j], wB[1], vc); fma2(accB[j], wB[2], vr);
            }
            if (j >= D && j < R + D) {
                fma2(accA[j - D], wA[3], vl); fma2(accA[j - D], wA[4], vc); fma2(accA[j - D], wA[5], vr);
                fma2(accB[j - D], wB[3], vl); fma2(accB[j - D], wB[4], vc); fma2(accB[j - D], wB[5], vr);
            }
            if (j >= 2 * D) {
                fma2(accA[j - 2 * D], wA[6], vl); fma2(accA[j - 2 * D], wA[7], vc); fma2(accA[j - 2 * D], wA[8], vr);
                fma2(accB[j - 2 * D], wB[6], vl); fma2(accB[j - 2 * D], wB[7], vc); fma2(accB[j - 2 * D], wB[8], vr);
            }
        }
        // no trailing sync needed: next fill targets buffer (ic+2)%3, and the
        // per-iteration barrier bounds stragglers to compute(ic-1) on (ic-1)%3.
    }

    float* oA = outg + ((size_t)(b * C_TOTAL + N_IN)) * CS
                     + (size_t)(r0 + rg * R) * Wdim + (c0 + 2 * tc);
    #pragma unroll
    for (int m = 0; m < R; ++m) {
        float lo, hi;
        unpack2(accA[m], lo, hi);
        *(float2*)(oA + (size_t)m * Wdim) = make_float2(fmaxf(lo, 0.f), fmaxf(hi, 0.f));
        unpack2(accB[m], lo, hi);
        *(float2*)(oA + CS + (size_t)m * Wdim) = make_float2(fmaxf(lo, 0.f), fmaxf(hi, 0.f));
    }
}

__global__ void copy_in_kernel(const float4* __restrict__ x, float4* __restrict__ out) {
    int idx = blockIdx.x * blockDim.x + threadIdx.x;
    const int P4 = CS / 4;
    if (idx >= Bdim * P4) return;
    int b = idx / P4;
    int p = idx - b * P4;
    out[(size_t)b * (C_TOTAL * P4) + p] = x[idx];
}

template<int N_IN, int D>
static void launch_layer(float* out, const float* w, const float* bias, int layer) {
    constexpr int PAD = (D + 3) & ~3;
    constexpr int TCW = 64 + 2 * PAD;
    constexpr int TROWS = 64 + 2 * D;
    constexpr int WS = (18 * N_IN + 3) & ~3;
    constexpr int SMEM = (WS + 3 * TROWS * TCW) * 4;
    cudaFuncSetAttribute(conv_layer<N_IN, D>,
                         cudaFuncAttributeMaxDynamicSharedMemorySize, SMEM);
    conv_layer<N_IN, D><<<dim3(Wdim / 64, Hdim / 64, Bdim), 128, SMEM>>>(
        out, out, w, bias + 2 * layer);
}

extern "C" void kernel_launch(void* const* d_in, const int* in_sizes, int n_in,
                              void* d_out, int out_size) {
    const float* x    = (const float*)d_in[0];
    const float* bias = (const float*)d_in[1];
    float* out = (float*)d_out;

    {
        int total4 = Bdim * CS / 4;
        copy_in_kernel<<<(total4 + 255) / 256, 256>>>((const float4*)x, (float4*)out);
    }

    launch_layer< 1,  1>(out, (const float*)d_in[2],  bias, 0);
    launch_layer< 3,  2>(out, (const float*)d_in[3],  bias, 1);
    launch_layer< 5,  3>(out, (const float*)d_in[4],  bias, 2);
    launch_layer< 7,  4>(out, (const float*)d_in[5],  bias, 3);
    launch_layer< 9,  5>(out, (const float*)d_in[6],  bias, 4);
    launch_layer<11,  6>(out, (const float*)d_in[7],  bias, 5);
    launch_layer<13,  7>(out, (const float*)d_in[8],  bias, 6);
    launch_layer<15,  8>(out, (const float*)d_in[9],  bias, 7);
    launch_layer<17,  9>(out, (const float*)d_in[10], bias, 8);
    launch_layer<19, 10>(out, (const float*)d_in[11], bias, 9);
    launch_layer<21, 11>(out, (const float*)d_in[12], bias, 10);
    launch_layer<23, 12>(out, (const float*)d_in[13], bias, 11);
}

// round 7
// speedup vs baseline: 1.2495x; 1.2482x over previous
#include <cuda_runtime.h>
#include <cstdint>

#define Bdim 4
#define Hdim 512
#define Wdim 512
#define C_TOTAL 25
#define CS (Hdim * Wdim)

typedef unsigned long long u64;

__device__ __forceinline__ void fma2(u64& d, u64 a, u64 b) {
    asm("fma.rn.f32x2 %0, %1, %2, %0;" : "+l"(d) : "l"(a), "l"(b));
}
__device__ __forceinline__ u64 dup2(float v) {
    u64 r; asm("mov.b64 %0, {%1, %1};" : "=l"(r) : "f"(v)); return r;
}
__device__ __forceinline__ u64 pack2(float lo, float hi) {
    u64 r; asm("mov.b64 %0, {%1, %2};" : "=l"(r) : "f"(lo), "f"(hi)); return r;
}
__device__ __forceinline__ void unpack2(u64 v, float& lo, float& hi) {
    asm("mov.b64 {%0, %1}, %2;" : "=f"(lo), "=f"(hi) : "l"(v));
}
__device__ __forceinline__ int refl(int x) {
    return x < 0 ? -x : (x >= Hdim ? 2 * Hdim - 2 - x : x);   // H==W==512
}

// ---------------------------------------------------------------------------
// Direct-LDG dilated 3x3 conv, column-pair f32x2 packed, row-stationary.
// Warp = 16 output rows x 64 cols (lane owns col pair (w, w+1), both out chans).
// Block = 128 threads = 4 stacked row-groups (64 rows x 64 cols tile).
// No shared memory, no synchronization. Taps stream through L1/L2.
// ---------------------------------------------------------------------------
template<int N_IN, int D, bool EDGE>
__device__ __forceinline__ void conv_tile(const float* __restrict__ g,
                                          float* __restrict__ outg,
                                          const float* __restrict__ wgt,
                                          const float* __restrict__ bias2p,
                                          int w, int r0, int b)
{
    constexpr int R = 16;

    u64 accA[R], accB[R];
    {
        u64 bA = dup2(bias2p[0]), bB = dup2(bias2p[1]);
        #pragma unroll
        for (int m = 0; m < R; ++m) { accA[m] = bA; accB[m] = bB; }
    }

    const float* plane0 = g + (size_t)(b * C_TOTAL) * CS;

    #pragma unroll 1
    for (int ic = 0; ic < N_IN; ++ic) {
        const float* plane = plane0 + (size_t)ic * CS;
        const float* wp = wgt + ic * 9;
        u64 wA[9], wB[9];
        #pragma unroll
        for (int k = 0; k < 9; ++k) {
            wA[k] = dup2(__ldg(wp + k));
            wB[k] = dup2(__ldg(wp + 9 * N_IN + k));
        }

        #pragma unroll
        for (int j = 0; j < R + 2 * D; ++j) {
            const int xr = refl(r0 - D + j);
            const float* row = plane + ((size_t)xr << 9);

            u64 vc = *(const u64*)(row + w);          // w even -> 8B aligned
            u64 vl, vr;
            if (EDGE) {
                int a0 = w - D, a1 = w + 1 - D, b0 = w + D, b1 = w + 1 + D;
                a0 = a0 < 0 ? -a0 : a0;  a1 = a1 < 0 ? -a1 : a1;
                b0 = b0 >= Wdim ? 2 * Wdim - 2 - b0 : b0;
                b1 = b1 >= Wdim ? 2 * Wdim - 2 - b1 : b1;
                vl = pack2(row[a0], row[a1]);
                vr = pack2(row[b0], row[b1]);
            } else if (D & 1) {
                vl = pack2(row[w - D], row[w + 1 - D]);
                vr = pack2(row[w + D], row[w + 1 + D]);
            } else {
                vl = *(const u64*)(row + w - D);
                vr = *(const u64*)(row + w + D);
            }
            // input row j feeds out-row m = j - kh*D with weight row kh
            if (j < R) {
                fma2(accA[j], wA[0], vl); fma2(accA[j], wA[1], vc); fma2(accA[j], wA[2], vr);
                fma2(accB[j], wB[0], vl); fma2(accB[j], wB[1], vc); fma2(accB[j], wB[2], vr);
            }
            if (j >= D && j < R + D) {
                fma2(accA[j - D], wA[3], vl); fma2(accA[j - D], wA[4], vc); fma2(accA[j - D], wA[5], vr);
                fma2(accB[j - D], wB[3], vl); fma2(accB[j - D], wB[4], vc); fma2(accB[j - D], wB[5], vr);
            }
            if (j >= 2 * D) {
                fma2(accA[j - 2 * D], wA[6], vl); fma2(accA[j - 2 * D], wA[7], vc); fma2(accA[j - 2 * D], wA[8], vr);
                fma2(accB[j - 2 * D], wB[6], vl); fma2(accB[j - 2 * D], wB[7], vc); fma2(accB[j - 2 * D], wB[8], vr);
            }
        }
    }

    float* o = outg + ((size_t)(b * C_TOTAL + N_IN)) * CS + (size_t)r0 * Wdim + w;
    #pragma unroll
    for (int m = 0; m < R; ++m) {
        float lo, hi;
        unpack2(accA[m], lo, hi);
        *(float2*)(o + (size_t)m * Wdim) = make_float2(fmaxf(lo, 0.f), fmaxf(hi, 0.f));
        unpack2(accB[m], lo, hi);
        *(float2*)(o + CS + (size_t)m * Wdim) = make_float2(fmaxf(lo, 0.f), fmaxf(hi, 0.f));
    }
}

template<int N_IN, int D>
__global__ __launch_bounds__(128)
void conv_layer(const float* __restrict__ g, float* __restrict__ outg,
                const float* __restrict__ wgt, const float* __restrict__ bias2p)
{
    const int tc = threadIdx.x & 31;          // column pair within warp
    const int rg = threadIdx.x >> 5;          // row group (warp) within block
    const int w  = blockIdx.x * 64 + 2 * tc;  // first of the 2 owned columns
    const int r0 = blockIdx.y * 64 + rg * 16;
    const int b  = blockIdx.z;

    // Only the first/last 64-col strips can touch a column reflect (D <= 12 < 64).
    if (blockIdx.x == 0 || blockIdx.x == (Wdim / 64) - 1)
        conv_tile<N_IN, D, true >(g, outg, wgt, bias2p, w, r0, b);
    else
        conv_tile<N_IN, D, false>(g, outg, wgt, bias2p, w, r0, b);
}

__global__ void copy_in_kernel(const float4* __restrict__ x, float4* __restrict__ out) {
    int idx = blockIdx.x * blockDim.x + threadIdx.x;
    const int P4 = CS / 4;
    if (idx >= Bdim * P4) return;
    int b = idx / P4;
    int p = idx - b * P4;
    out[(size_t)b * (C_TOTAL * P4) + p] = x[idx];
}

template<int N_IN, int D>
static void launch_layer(float* out, const float* w, const float* bias, int layer) {
    conv_layer<N_IN, D><<<dim3(Wdim / 64, Hdim / 64, Bdim), 128>>>(
        out, out, w, bias + 2 * layer);
}

extern "C" void kernel_launch(void* const* d_in, const int* in_sizes, int n_in,
                              void* d_out, int out_size) {
    const float* x    = (const float*)d_in[0];
    const float* bias = (const float*)d_in[1];
    float* out = (float*)d_out;

    {
        int total4 = Bdim * CS / 4;
        copy_in_kernel<<<(total4 + 255) / 256, 256>>>((const float4*)x, (float4*)out);
    }

    launch_layer< 1,  1>(out, (const float*)d_in[2],  bias, 0);
    launch_layer< 3,  2>(out, (const float*)d_in[3],  bias, 1);
    launch_layer< 5,  3>(out, (const float*)d_in[4],  bias, 2);
    launch_layer< 7,  4>(out, (const float*)d_in[5],  bias, 3);
    launch_layer< 9,  5>(out, (const float*)d_in[6],  bias, 4);
    launch_layer<11,  6>(out, (const float*)d_in[7],  bias, 5);
    launch_layer<13,  7>(out, (const float*)d_in[8],  bias, 6);
    launch_layer<15,  8>(out, (const float*)d_in[9],  bias, 7);
    launch_layer<17,  9>(out, (const float*)d_in[10], bias, 8);
    launch_layer<19, 10>(out, (const float*)d_in[11], bias, 9);
    launch_layer<21, 11>(out, (const float*)d_in[12], bias, 10);
    launch_layer<23, 12>(out, (const float*)d_in[13], bias, 11);
}